// round 14
// baseline (speedup 1.0000x reference)
#include <cuda_runtime.h>
#include <cuda_bf16.h>

// Shapes from the reference: N=100000, E=1600000, F_in=256, F_hid=64, F_out=40
#define MAX_N 100000
#define MAX_E 1600000
#define F_IN  256
#define F_HID 64
#define F_OUT 40

// Scratch (device globals; no allocation allowed)
__device__ float g_h1[MAX_N * F_HID];    // x @ W1
__device__ float g_a1[MAX_N * F_HID];    // aggregated layer-1 output (pre-bias/relu)
__device__ float g_h2[MAX_N * F_OUT];    // relu(a1+b1) @ W2
__device__ float g_dis[MAX_N];           // deg, then rsqrt(deg) in place
__device__ float g_norm[MAX_E];          // per-edge norm = dis[row]*ew*dis[col]
__device__ int2  g_rc[MAX_E];            // packed (row, col) as int32
__device__ int   g_is64;                 // 1 if edge_index is int64, 0 if int32

// ---------------- dtype detection ----------------
// Probe ONLY the first 32 8-byte words: in-bounds under both interpretations
// (an int32 buffer still holds 2*E*4 = 8E bytes >= 256). If edge_index is
// int64 with values in [0,N), every probed word is < N. If int32, word i
// fuses two random indices (row_{2i} | row_{2i+1}<<32) -> >= 2^32 unless the
// odd index is 0; misdetection probability ~ N^-32.

__global__ void detect_kernel(const void* __restrict__ ei, int E, int N) {
    if (threadIdx.x != 0 || blockIdx.x != 0) return;
    const long long* p = (const long long*)ei;
    int ok = 1;
    for (int i = 0; i < 32; i++) {
        long long a = p[i];
        if (a < 0 || a >= N) { ok = 0; break; }
    }
    g_is64 = ok;
}

__device__ __forceinline__ int load_idx(const void* ei, long long pos) {
    return g_is64 ? (int)((const long long*)ei)[pos] : ((const int*)ei)[pos];
}

// ---------------- degree / norm ----------------

__global__ void init_deg_kernel(int N) {
    int i = blockIdx.x * blockDim.x + threadIdx.x;
    if (i < N) g_dis[i] = 1.0f;   // self-loop weight 1 folded in
}

__global__ void deg_accum_kernel(const void* __restrict__ ei,
                                 const float* __restrict__ ew, int E) {
    int e = blockIdx.x * blockDim.x + threadIdx.x;
    if (e >= E) return;
    int col = load_idx(ei, (long long)E + e);
    atomicAdd(&g_dis[col], ew[e]);
}

__global__ void rsqrt_kernel(int N) {
    int i = blockIdx.x * blockDim.x + threadIdx.x;
    if (i < N) g_dis[i] = rsqrtf(g_dis[i]);   // deg >= 1 always (self loop)
}

// also packs (row,col) into int2 for the agg kernels
__global__ void norm_kernel(const void* __restrict__ ei,
                            const float* __restrict__ ew, int E) {
    int e = blockIdx.x * blockDim.x + threadIdx.x;
    if (e >= E) return;
    int r   = load_idx(ei, e);
    int col = load_idx(ei, (long long)E + e);
    g_rc[e] = make_int2(r, col);
    g_norm[e] = g_dis[r] * ew[e] * g_dis[col];
}

// ---------------- GEMM1: h1 = x @ W1  (N x 256) * (256 x 64) ----------------
// 64x64 block tile, BK=32, 256 threads, 4x4 register micro-tile.

__global__ __launch_bounds__(256) void gemm1_kernel(const float* __restrict__ x,
                                                    const float* __restrict__ W1, int N) {
    __shared__ float Xs[64][32];
    __shared__ float Ws[32][64];
    int tid = threadIdx.x;
    int tx = tid & 15;        // 0..15 -> output feature group
    int ty = tid >> 4;        // 0..15 -> node group
    int m0 = blockIdx.x * 64;

    float acc[4][4] = {};

    for (int kt = 0; kt < F_IN; kt += 32) {
        // Load X tile: 64x32 floats = 512 float4 slots
        #pragma unroll
        for (int i = 0; i < 2; i++) {
            int s  = tid + i * 256;
            int r  = s >> 3;
            int c4 = s & 7;
            float4 v = make_float4(0.f, 0.f, 0.f, 0.f);
            int gr = m0 + r;
            if (gr < N) v = *(const float4*)&x[(long long)gr * F_IN + kt + c4 * 4];
            *(float4*)&Xs[r][c4 * 4] = v;
        }
        // Load W tile: 32x64 floats = 512 float4 slots
        #pragma unroll
        for (int i = 0; i < 2; i++) {
            int s  = tid + i * 256;
            int r  = s >> 4;
            int c4 = s & 15;
            *(float4*)&Ws[r][c4 * 4] = *(const float4*)&W1[(kt + r) * F_HID + c4 * 4];
        }
        __syncthreads();

        #pragma unroll
        for (int k = 0; k < 32; k++) {
            float a[4], b[4];
            #pragma unroll
            for (int i = 0; i < 4; i++) a[i] = Xs[ty * 4 + i][k];
            #pragma unroll
            for (int j = 0; j < 4; j++) b[j] = Ws[k][tx * 4 + j];
            #pragma unroll
            for (int i = 0; i < 4; i++)
                #pragma unroll
                for (int j = 0; j < 4; j++)
                    acc[i][j] = fmaf(a[i], b[j], acc[i][j]);
        }
        __syncthreads();
    }

    #pragma unroll
    for (int i = 0; i < 4; i++) {
        int m = m0 + ty * 4 + i;
        if (m < N) {
            #pragma unroll
            for (int j = 0; j < 4; j++)
                g_h1[(long long)m * F_HID + tx * 4 + j] = acc[i][j];
        }
    }
}

// ---------------- layer-1 aggregation ----------------

// a1[i] = dis[i]^2 * h1[i]  (self-loop term), then atomics add edge messages
__global__ void init_a1_kernel(int N) {
    int idx = blockIdx.x * blockDim.x + threadIdx.x;
    if (idx >= N * F_HID) return;
    int n = idx >> 6;   // /64
    float d = g_dis[n];
    g_a1[idx] = d * d * g_h1[idx];
}

// one thread per (edge, float4-chunk): 16 chunks of 4 floats per edge
__global__ void agg1_kernel(int E) {
    long long idx = (long long)blockIdx.x * blockDim.x + threadIdx.x;
    if (idx >= (long long)E * 16) return;
    int e = (int)(idx >> 4);
    int c = (int)(idx & 15);
    int2 rc = __ldg(&g_rc[e]);
    float nrm = __ldg(&g_norm[e]);
    float4 v = __ldg(((const float4*)&g_h1[(long long)rc.x * F_HID]) + c);
    float* dst = &g_a1[(long long)rc.y * F_HID + c * 4];
    atomicAdd(dst + 0, nrm * v.x);
    atomicAdd(dst + 1, nrm * v.y);
    atomicAdd(dst + 2, nrm * v.z);
    atomicAdd(dst + 3, nrm * v.w);
}

// ---------------- GEMM2: h2 = relu(a1 + b1) @ W2  (N x 64) * (64 x 40) ----------------
// 4 nodes per block, 256 threads, W2 staged in shared.

__global__ __launch_bounds__(256) void gemm2_kernel(const float* __restrict__ b1,
                                                    const float* __restrict__ W2, int N) {
    __shared__ float W2s[F_HID * F_OUT];
    __shared__ float hs[4][F_HID];
    int tid = threadIdx.x;
    for (int i = tid; i < F_HID * F_OUT; i += 256) W2s[i] = W2[i];

    int local = tid >> 6;       // 0..3
    int t     = tid & 63;       // 0..63
    int n = blockIdx.x * 4 + local;
    float hv = 0.f;
    if (n < N) hv = fmaxf(g_a1[(long long)n * F_HID + t] + b1[t], 0.f);
    hs[local][t] = hv;
    __syncthreads();

    if (t < F_OUT && n < N) {
        float acc = 0.f;
        #pragma unroll
        for (int k = 0; k < F_HID; k++)
            acc = fmaf(hs[local][k], W2s[k * F_OUT + t], acc);
        g_h2[(long long)n * F_OUT + t] = acc;
    }
}

// ---------------- layer-2 aggregation into d_out ----------------

__global__ void init_out_kernel(float* __restrict__ out,
                                const float* __restrict__ b2, int N) {
    int idx = blockIdx.x * blockDim.x + threadIdx.x;
    if (idx >= N * F_OUT) return;
    int n = idx / F_OUT;
    int f = idx - n * F_OUT;
    float d = g_dis[n];
    out[idx] = d * d * g_h2[idx] + b2[f];
}

// one thread per (edge, float4-chunk): 10 chunks of 4 floats per edge
__global__ void agg2_kernel(float* __restrict__ out, int E) {
    long long idx = (long long)blockIdx.x * blockDim.x + threadIdx.x;
    if (idx >= (long long)E * 10) return;
    int e = (int)(idx / 10);
    int c = (int)(idx - (long long)e * 10);
    int2 rc = __ldg(&g_rc[e]);
    float nrm = __ldg(&g_norm[e]);
    float4 v = __ldg(((const float4*)&g_h2[(long long)rc.x * F_OUT]) + c);
    float* dst = &out[(long long)rc.y * F_OUT + c * 4];
    atomicAdd(dst + 0, nrm * v.x);
    atomicAdd(dst + 1, nrm * v.y);
    atomicAdd(dst + 2, nrm * v.z);
    atomicAdd(dst + 3, nrm * v.w);
}

// ---------------- launch ----------------

extern "C" void kernel_launch(void* const* d_in, const int* in_sizes, int n_in,
                              void* d_out, int out_size) {
    const float* x  = (const float*)d_in[0];
    const void*  ei = d_in[1];                 // dtype detected on device
    const float* ew = (const float*)d_in[2];
    const float* W1 = (const float*)d_in[3];
    const float* b1 = (const float*)d_in[4];
    const float* W2 = (const float*)d_in[5];
    const float* b2 = (const float*)d_in[6];
    float* out = (float*)d_out;

    int N = in_sizes[0] / F_IN;
    int E = in_sizes[2];

    const int T = 256;

    // dtype probe + degree + norm
    detect_kernel<<<1, 1>>>(ei, E, N);
    init_deg_kernel<<<(N + T - 1) / T, T>>>(N);
    deg_accum_kernel<<<(E + T - 1) / T, T>>>(ei, ew, E);
    rsqrt_kernel<<<(N + T - 1) / T, T>>>(N);
    norm_kernel<<<(E + T - 1) / T, T>>>(ei, ew, E);

    // layer 1
    gemm1_kernel<<<(N + 63) / 64, 256>>>(x, W1, N);
    init_a1_kernel<<<(N * F_HID + T - 1) / T, T>>>(N);
    {
        long long work = (long long)E * 16;
        int blocks = (int)((work + T - 1) / T);
        agg1_kernel<<<blocks, T>>>(E);
    }

    // layer 2
    gemm2_kernel<<<(N + 3) / 4, 256>>>(b1, W2, N);
    init_out_kernel<<<(N * F_OUT + T - 1) / T, T>>>(out, b2, N);
    {
        long long work = (long long)E * 10;
        int blocks = (int)((work + T - 1) / T);
        agg2_kernel<<<blocks, T>>>(out, E);
    }
}

// round 16
// speedup vs baseline: 1.4609x; 1.4609x over previous
#include <cuda_runtime.h>
#include <cuda_bf16.h>

// Shapes from the reference: N=100000, E=1600000, F_in=256, F_hid=64, F_out=40
#define MAX_N 100000
#define MAX_E 1600000
#define F_IN  256
#define F_HID 64
#define F_OUT 40

// Scratch (device globals; no allocation allowed)
__device__ float g_h1[MAX_N * F_HID];    // x @ W1
__device__ float g_a1[MAX_N * F_HID];    // aggregated layer-1 output (pre-bias/relu)
__device__ float g_h2[MAX_N * F_OUT];    // relu(a1+b1) @ W2
__device__ float g_dis[MAX_N];           // deg, then rsqrt(deg) in place
__device__ float g_norm[MAX_E];          // per-edge norm = dis[row]*ew*dis[col]
__device__ int2  g_rc[MAX_E];            // packed (row, col) as int32
__device__ int   g_is64;                 // 1 if edge_index is int64, 0 if int32

// R14 insight: the 717 trap was garbage addresses from misreading int32
// edge_index as int64 — NOT v4 reductions. Re-testing vector RED now.
__device__ __forceinline__ void red_add_v4(float* p, float a, float b, float c, float d) {
    asm volatile("red.global.add.v4.f32 [%0], {%1, %2, %3, %4};"
                 :: "l"(p), "f"(a), "f"(b), "f"(c), "f"(d)
                 : "memory");
}

// ---------------- dtype detection ----------------
// Probe ONLY the first 32 8-byte words: in-bounds under both interpretations
// (an int32 buffer still holds 2*E*4 = 8E bytes >= 256). If edge_index is
// int64 with values in [0,N), every probed word is < N. If int32, word i
// fuses two random indices -> >= 2^32 unless the odd index is 0.

__global__ void detect_kernel(const void* __restrict__ ei, int E, int N) {
    if (threadIdx.x != 0 || blockIdx.x != 0) return;
    const long long* p = (const long long*)ei;
    int ok = 1;
    for (int i = 0; i < 32; i++) {
        long long a = p[i];
        if (a < 0 || a >= N) { ok = 0; break; }
    }
    g_is64 = ok;
}

__device__ __forceinline__ int load_idx(const void* ei, long long pos) {
    return g_is64 ? (int)((const long long*)ei)[pos] : ((const int*)ei)[pos];
}

// ---------------- degree / norm ----------------

__global__ void init_deg_kernel(int N) {
    int i = blockIdx.x * blockDim.x + threadIdx.x;
    if (i < N) g_dis[i] = 1.0f;   // self-loop weight 1 folded in
}

__global__ void deg_accum_kernel(const void* __restrict__ ei,
                                 const float* __restrict__ ew, int E) {
    int e = blockIdx.x * blockDim.x + threadIdx.x;
    if (e >= E) return;
    int col = load_idx(ei, (long long)E + e);
    atomicAdd(&g_dis[col], ew[e]);
}

__global__ void rsqrt_kernel(int N) {
    int i = blockIdx.x * blockDim.x + threadIdx.x;
    if (i < N) g_dis[i] = rsqrtf(g_dis[i]);   // deg >= 1 always (self loop)
}

// also packs (row,col) into int2 for the agg kernels
__global__ void norm_kernel(const void* __restrict__ ei,
                            const float* __restrict__ ew, int E) {
    int e = blockIdx.x * blockDim.x + threadIdx.x;
    if (e >= E) return;
    int r   = load_idx(ei, e);
    int col = load_idx(ei, (long long)E + e);
    g_rc[e] = make_int2(r, col);
    g_norm[e] = g_dis[r] * ew[e] * g_dis[col];
}

// ---------------- GEMM1: h1 = x @ W1  (N x 256) * (256 x 64) ----------------
// 64x64 block tile, BK=32, 256 threads, 4x4 register micro-tile.

__global__ __launch_bounds__(256) void gemm1_kernel(const float* __restrict__ x,
                                                    const float* __restrict__ W1, int N) {
    __shared__ float Xs[64][32];
    __shared__ float Ws[32][64];
    int tid = threadIdx.x;
    int tx = tid & 15;        // 0..15 -> output feature group
    int ty = tid >> 4;        // 0..15 -> node group
    int m0 = blockIdx.x * 64;

    float acc[4][4] = {};

    for (int kt = 0; kt < F_IN; kt += 32) {
        // Load X tile: 64x32 floats = 512 float4 slots
        #pragma unroll
        for (int i = 0; i < 2; i++) {
            int s  = tid + i * 256;
            int r  = s >> 3;
            int c4 = s & 7;
            float4 v = make_float4(0.f, 0.f, 0.f, 0.f);
            int gr = m0 + r;
            if (gr < N) v = *(const float4*)&x[(long long)gr * F_IN + kt + c4 * 4];
            *(float4*)&Xs[r][c4 * 4] = v;
        }
        // Load W tile: 32x64 floats = 512 float4 slots
        #pragma unroll
        for (int i = 0; i < 2; i++) {
            int s  = tid + i * 256;
            int r  = s >> 4;
            int c4 = s & 15;
            *(float4*)&Ws[r][c4 * 4] = *(const float4*)&W1[(kt + r) * F_HID + c4 * 4];
        }
        __syncthreads();

        #pragma unroll
        for (int k = 0; k < 32; k++) {
            float a[4], b[4];
            #pragma unroll
            for (int i = 0; i < 4; i++) a[i] = Xs[ty * 4 + i][k];
            #pragma unroll
            for (int j = 0; j < 4; j++) b[j] = Ws[k][tx * 4 + j];
            #pragma unroll
            for (int i = 0; i < 4; i++)
                #pragma unroll
                for (int j = 0; j < 4; j++)
                    acc[i][j] = fmaf(a[i], b[j], acc[i][j]);
        }
        __syncthreads();
    }

    #pragma unroll
    for (int i = 0; i < 4; i++) {
        int m = m0 + ty * 4 + i;
        if (m < N) {
            #pragma unroll
            for (int j = 0; j < 4; j++)
                g_h1[(long long)m * F_HID + tx * 4 + j] = acc[i][j];
        }
    }
}

// ---------------- layer-1 aggregation ----------------

// a1[i] = dis[i]^2 * h1[i]  (self-loop term), then atomics add edge messages
__global__ void init_a1_kernel(int N) {
    int idx = blockIdx.x * blockDim.x + threadIdx.x;
    if (idx >= N * F_HID) return;
    int n = idx >> 6;   // /64
    float d = g_dis[n];
    g_a1[idx] = d * d * g_h1[idx];
}

// one thread per (edge, float4-chunk): 16 chunks of 4 floats per edge
__global__ void agg1_kernel(int E) {
    long long idx = (long long)blockIdx.x * blockDim.x + threadIdx.x;
    if (idx >= (long long)E * 16) return;
    int e = (int)(idx >> 4);
    int c = (int)(idx & 15);
    int2 rc = __ldg(&g_rc[e]);
    float nrm = __ldg(&g_norm[e]);
    float4 v = __ldg(((const float4*)&g_h1[(long long)rc.x * F_HID]) + c);
    red_add_v4(&g_a1[(long long)rc.y * F_HID + c * 4],
               nrm * v.x, nrm * v.y, nrm * v.z, nrm * v.w);
}

// ---------------- GEMM2: h2 = relu(a1 + b1) @ W2  (N x 64) * (64 x 40) ----------------
// 4 nodes per block, 256 threads, W2 staged in shared.

__global__ __launch_bounds__(256) void gemm2_kernel(const float* __restrict__ b1,
                                                    const float* __restrict__ W2, int N) {
    __shared__ float W2s[F_HID * F_OUT];
    __shared__ float hs[4][F_HID];
    int tid = threadIdx.x;
    for (int i = tid; i < F_HID * F_OUT; i += 256) W2s[i] = W2[i];

    int local = tid >> 6;       // 0..3
    int t     = tid & 63;       // 0..63
    int n = blockIdx.x * 4 + local;
    float hv = 0.f;
    if (n < N) hv = fmaxf(g_a1[(long long)n * F_HID + t] + b1[t], 0.f);
    hs[local][t] = hv;
    __syncthreads();

    if (t < F_OUT && n < N) {
        float acc = 0.f;
        #pragma unroll
        for (int k = 0; k < F_HID; k++)
            acc = fmaf(hs[local][k], W2s[k * F_OUT + t], acc);
        g_h2[(long long)n * F_OUT + t] = acc;
    }
}

// ---------------- layer-2 aggregation into d_out ----------------

__global__ void init_out_kernel(float* __restrict__ out,
                                const float* __restrict__ b2, int N) {
    int idx = blockIdx.x * blockDim.x + threadIdx.x;
    if (idx >= N * F_OUT) return;
    int n = idx / F_OUT;
    int f = idx - n * F_OUT;
    float d = g_dis[n];
    out[idx] = d * d * g_h2[idx] + b2[f];
}

// one thread per (edge, float4-chunk): 10 chunks of 4 floats per edge
__global__ void agg2_kernel(float* __restrict__ out, int E) {
    long long idx = (long long)blockIdx.x * blockDim.x + threadIdx.x;
    if (idx >= (long long)E * 10) return;
    int e = (int)(idx / 10);
    int c = (int)(idx - (long long)e * 10);
    int2 rc = __ldg(&g_rc[e]);
    float nrm = __ldg(&g_norm[e]);
    float4 v = __ldg(((const float4*)&g_h2[(long long)rc.x * F_OUT]) + c);
    red_add_v4(&out[(long long)rc.y * F_OUT + c * 4],
               nrm * v.x, nrm * v.y, nrm * v.z, nrm * v.w);
}

// ---------------- launch ----------------

extern "C" void kernel_launch(void* const* d_in, const int* in_sizes, int n_in,
                              void* d_out, int out_size) {
    const float* x  = (const float*)d_in[0];
    const void*  ei = d_in[1];                 // dtype detected on device
    const float* ew = (const float*)d_in[2];
    const float* W1 = (const float*)d_in[3];
    const float* b1 = (const float*)d_in[4];
    const float* W2 = (const float*)d_in[5];
    const float* b2 = (const float*)d_in[6];
    float* out = (float*)d_out;

    int N = in_sizes[0] / F_IN;
    int E = in_sizes[2];

    const int T = 256;

    // dtype probe + degree + norm
    detect_kernel<<<1, 1>>>(ei, E, N);
    init_deg_kernel<<<(N + T - 1) / T, T>>>(N);
    deg_accum_kernel<<<(E + T - 1) / T, T>>>(ei, ew, E);
    rsqrt_kernel<<<(N + T - 1) / T, T>>>(N);
    norm_kernel<<<(E + T - 1) / T, T>>>(ei, ew, E);

    // layer 1
    gemm1_kernel<<<(N + 63) / 64, 256>>>(x, W1, N);
    init_a1_kernel<<<(N * F_HID + T - 1) / T, T>>>(N);
    {
        long long work = (long long)E * 16;
        int blocks = (int)((work + T - 1) / T);
        agg1_kernel<<<blocks, T>>>(E);
    }

    // layer 2
    gemm2_kernel<<<(N + 3) / 4, 256>>>(b1, W2, N);
    init_out_kernel<<<(N * F_OUT + T - 1) / T, T>>>(out, b2, N);
    {
        long long work = (long long)E * 10;
        int blocks = (int)((work + T - 1) / T);
        agg2_kernel<<<blocks, T>>>(out, E);
    }
}